// round 10
// baseline (speedup 1.0000x reference)
#include <cuda_runtime.h>
#include <cuda_fp16.h>
#include <cstdint>
#include <math.h>

#define NTOK 8192
#define NE   8
#define DDIM 1024
#define HDIM 5632
#define H2   (2*HDIM)
#define CAP  1280

#define OUT_AUX  8388608
#define OUT_TOP  (8388608 + 1)
#define OUT_KEEP (8388608 + 1 + NTOK)

// ---------------- scratch ----------------
__device__ float d_probs[NTOK * NE];
__device__ float d_z2[NTOK];
__device__ int   d_top[NTOK];
__device__ int   d_keep[NTOK];
__device__ int   d_gidx[NE * CAP];
__device__ int   d_counts[NE];
__device__ int   d_counts_cap[NE];
__device__ __align__(256) __half d_hh[(size_t)NE * CAP * HDIM];     // 115 MB
__device__ __align__(256) __half d_xh[(size_t)NTOK * DDIM];         //  17 MB
__device__ __align__(256) __half d_w13h[(size_t)NE * H2 * DDIM];    // 184 MB
__device__ __align__(256) __half d_w2h[(size_t)NE * DDIM * HDIM];   //  92 MB

// ---------------- helpers ----------------
__device__ __forceinline__ uint32_t smem_u32(const void* p) {
    uint32_t a;
    asm("{ .reg .u64 t; cvta.to.shared.u64 t, %1; cvt.u32.u64 %0, t; }"
        : "=r"(a) : "l"(p));
    return a;
}
__device__ __forceinline__ uint32_t h2_u32(__half2 h) {
    return *reinterpret_cast<uint32_t*>(&h);
}
__device__ __forceinline__ void mma_f16(float* c, const uint32_t* a,
                                        uint32_t b0, uint32_t b1) {
    asm volatile(
        "mma.sync.aligned.m16n8k16.row.col.f32.f16.f16.f32 "
        "{%0,%1,%2,%3}, {%4,%5,%6,%7}, {%8,%9}, {%0,%1,%2,%3};"
        : "+f"(c[0]), "+f"(c[1]), "+f"(c[2]), "+f"(c[3])
        : "r"(a[0]), "r"(a[1]), "r"(a[2]), "r"(a[3]), "r"(b0), "r"(b1));
}
#define LDSM4(r0, r1, r2, r3, a) \
    asm volatile("ldmatrix.sync.aligned.m8n8.x4.shared.b16 {%0,%1,%2,%3}, [%4];" \
                 : "=r"(r0), "=r"(r1), "=r"(r2), "=r"(r3) : "r"(a))
#define CP16(d, s) \
    asm volatile("cp.async.cg.shared.global [%0], [%1], 16;" :: "r"(d), "l"(s))
#define CPCOMMIT() asm volatile("cp.async.commit_group;")
#define CPWAIT1()  asm volatile("cp.async.wait_group 1;")

// ---------------- 0. fp32 -> fp16 conversion ----------------
__global__ void cvt_kernel(const float4* __restrict__ src,
                           uint2* __restrict__ dst, int n4)
{
    int i = blockIdx.x * blockDim.x + threadIdx.x;
    if (i < n4) {
        float4 v = src[i];
        __half2 lo = __floats2half2_rn(v.x, v.y);
        __half2 hi = __floats2half2_rn(v.z, v.w);
        dst[i] = make_uint2(h2_u32(lo), h2_u32(hi));
    }
}

// ---------------- 1. router ----------------
__global__ void router_kernel(const float* __restrict__ x,
                              const float* __restrict__ Wg)
{
    __shared__ float sWg[NE * DDIM];
    int t = threadIdx.x;
    for (int i = t; i < NE * DDIM; i += 256) sWg[i] = Wg[i];
    __syncthreads();

    int warp = t >> 5, lane = t & 31;
    int tok  = blockIdx.x * 8 + warp;
    const float* xr = x + (size_t)tok * DDIM;

    float acc[NE];
#pragma unroll
    for (int e = 0; e < NE; e++) acc[e] = 0.f;
    for (int k = lane; k < DDIM; k += 32) {
        float xv = xr[k];
#pragma unroll
        for (int e = 0; e < NE; e++) acc[e] = fmaf(xv, sWg[e * DDIM + k], acc[e]);
    }
#pragma unroll
    for (int e = 0; e < NE; e++) {
#pragma unroll
        for (int o = 16; o > 0; o >>= 1)
            acc[e] += __shfl_down_sync(0xffffffffu, acc[e], o);
    }
    if (lane == 0) {
        float m = acc[0]; int am = 0;
#pragma unroll
        for (int e = 1; e < NE; e++) if (acc[e] > m) { m = acc[e]; am = e; }
        float p[NE]; float s = 0.f;
#pragma unroll
        for (int e = 0; e < NE; e++) { p[e] = expf(acc[e] - m); s += p[e]; }
        float inv = 1.f / s;
#pragma unroll
        for (int e = 0; e < NE; e++) d_probs[tok * NE + e] = p[e] * inv;
        float z = m + logf(s);
        d_z2[tok] = z * z;
        d_top[tok] = am;
    }
}

// ---------------- 2. ordered capacity scan (shfl-based) ----------------
__global__ void scan_kernel()
{
    __shared__ unsigned long long wsum0[32], wsum1[32];
    __shared__ unsigned long long tile0, tile1;
    __shared__ int base[NE];
    const int t = threadIdx.x, lane = t & 31, wid = t >> 5;
    if (t < NE) base[t] = 0;
    __syncthreads();

    for (int tile = 0; tile < NTOK / 1024; tile++) {
        int i = tile * 1024 + t;
        int e = d_top[i];
        unsigned long long v0 = (e < 4)  ? (1ULL << (16 * e))       : 0ULL;
        unsigned long long v1 = (e >= 4) ? (1ULL << (16 * (e - 4))) : 0ULL;
        unsigned long long s0 = v0, s1 = v1;
#pragma unroll
        for (int o = 1; o < 32; o <<= 1) {
            unsigned long long a0 = __shfl_up_sync(0xffffffffu, s0, o);
            unsigned long long a1 = __shfl_up_sync(0xffffffffu, s1, o);
            if (lane >= o) { s0 += a0; s1 += a1; }
        }
        if (lane == 31) { wsum0[wid] = s0; wsum1[wid] = s1; }
        __syncthreads();
        if (wid == 0) {
            unsigned long long w0 = wsum0[lane], w1 = wsum1[lane];
            unsigned long long p0 = w0, p1 = w1;
#pragma unroll
            for (int o = 1; o < 32; o <<= 1) {
                unsigned long long a0 = __shfl_up_sync(0xffffffffu, p0, o);
                unsigned long long a1 = __shfl_up_sync(0xffffffffu, p1, o);
                if (lane >= o) { p0 += a0; p1 += a1; }
            }
            wsum0[lane] = p0 - w0;       // exclusive warp offsets
            wsum1[lane] = p1 - w1;
            if (lane == 31) { tile0 = p0; tile1 = p1; }
        }
        __syncthreads();
        unsigned long long inc = (e < 4) ? (s0 + wsum0[wid]) : (s1 + wsum1[wid]);
        int sh  = 16 * (e & 3);
        int pos = base[e] + (int)((inc >> sh) & 0xFFFFULL) - 1;
        int kp  = (pos < CAP) ? 1 : 0;
        d_keep[i] = kp;
        if (kp) d_gidx[e * CAP + pos] = i;
        __syncthreads();
        if (t < 4)      base[t] += (int)((tile0 >> (16 * t)) & 0xFFFFULL);
        else if (t < 8) base[t] += (int)((tile1 >> (16 * (t - 4))) & 0xFFFFULL);
        __syncthreads();
    }
    if (t < NE) {
        d_counts[t] = base[t];
        d_counts_cap[t] = base[t] < CAP ? base[t] : CAP;
    }
}

// ---------------- 3. aux loss ----------------
__global__ void reduce_kernel(float* __restrict__ out_aux)
{
    __shared__ float sm[1024];
    __shared__ float pe[NE];
    int t = threadIdx.x;
    float pp[NE];
#pragma unroll
    for (int e = 0; e < NE; e++) pp[e] = 0.f;
    float zz = 0.f;
    for (int i = t; i < NTOK; i += 1024) {
#pragma unroll
        for (int e = 0; e < NE; e++) pp[e] += d_probs[i * NE + e];
        zz += d_z2[i];
    }
#pragma unroll
    for (int e = 0; e < NE; e++) {
        sm[t] = pp[e]; __syncthreads();
        for (int o = 512; o > 0; o >>= 1) {
            if (t < o) sm[t] += sm[t + o];
            __syncthreads();
        }
        if (t == 0) pe[e] = sm[0];
        __syncthreads();
    }
    sm[t] = zz; __syncthreads();
    for (int o = 512; o > 0; o >>= 1) {
        if (t < o) sm[t] += sm[t + o];
        __syncthreads();
    }
    if (t == 0) {
        float bal = 0.f;
        for (int e = 0; e < NE; e++)
            bal += (pe[e] / (float)NTOK) * ((float)d_counts[e] / (float)NTOK);
        bal *= 0.01f * (float)NE;
        out_aux[0] = bal + (sm[0] / (float)NTOK) * 0.001f;
    }
}

// ---------------- 4/5. fp16 mma.sync GEMMs, per-expert launches ------------
#define STG_B  32768               // bytes per stage (A 16KB + B 16KB)
#define SMEM_G (3 * STG_B)         // 98304 B

template<int MODE>
__global__ __launch_bounds__(256, 2)
void moe_gemm(float* __restrict__ out, int e)
{
    constexpr int KT  = (MODE == 0) ? DDIM / 64 : HDIM / 64;
    constexpr int WNS = (MODE == 0) ? 32 : 64;   // warpN stride (n cols)
    constexpr int NO2 = (MODE == 0) ? 64 : 32;   // row offset of second acc set

    extern __shared__ char smc[];
    __shared__ int s_tok[128];

    const int t = threadIdx.x, wid = t >> 5, lane = t & 31;
    const int lc = lane & 3;
    const int warpM = wid & 3, warpN = wid >> 2;
    const int m0 = blockIdx.x * 128, nb = blockIdx.y;

    const int cc = d_counts_cap[e];
    if (m0 >= cc) return;            // dead capacity rows: outputs never read

    if (t < 128)
        s_tok[t] = (m0 + t < cc) ? d_gidx[e * CAP + m0 + t] : ((MODE == 0) ? 0 : -1);
    __syncthreads();

    const uint32_t sbase = smem_u32(smc);
    const int lrow = t >> 1;           // loader row 0..127
    const int q0l  = (t & 1) * 4;      // first of 4 chunks

    auto load_stage = [&](int kt, int s) {
        const uint32_t ab = sbase + (uint32_t)s * STG_B;
        const uint32_t bb = ab + 16384;
        const int k0 = kt * 64;
#pragma unroll
        for (int c = 0; c < 4; c++) {
            int q = q0l + c;
            uint32_t dsw = (uint32_t)(lrow * 128 + ((q ^ (lrow & 7)) << 4));
            const __half* srcA;
            if (MODE == 0)
                srcA = d_xh + (size_t)s_tok[lrow] * DDIM + k0 + q * 8;
            else
                srcA = d_hh + ((size_t)e * CAP + m0 + lrow) * HDIM + k0 + q * 8;
            CP16(ab + dsw, srcA);
            const __half* srcB;
            if (MODE == 0) {
                int wr = (lrow < 64) ? (nb * 64 + lrow)
                                     : (HDIM + nb * 64 + lrow - 64);
                srcB = d_w13h + ((size_t)e * H2 + wr) * DDIM + k0 + q * 8;
            } else {
                srcB = d_w2h + ((size_t)e * DDIM + nb * 128 + lrow) * HDIM + k0 + q * 8;
            }
            CP16(bb + dsw, srcB);
        }
    };

    float c0[2][4][4], c1[2][4][4];
#pragma unroll
    for (int a = 0; a < 2; a++)
#pragma unroll
        for (int b = 0; b < 4; b++)
#pragma unroll
            for (int r = 0; r < 4; r++) { c0[a][b][r] = 0.f; c1[a][b][r] = 0.f; }

    const int rA  = warpM * 32 + (lane & 15);        // + mf*16
    const int cselA = lane >> 4;
    const int rB  = (lane & 7) + ((lane & 16) >> 1);
    const int cselB = (lane >> 3) & 1;

    load_stage(0, 0); CPCOMMIT();
    load_stage(1, 1); CPCOMMIT();

    for (int kt = 0; kt < KT; kt++) {
        CPWAIT1();
        __syncthreads();
        if (kt + 2 < KT) load_stage(kt + 2, (kt + 2) % 3);
        CPCOMMIT();

        const uint32_t ab = sbase + (uint32_t)(kt % 3) * STG_B;
        const uint32_t bb = ab + 16384;
#pragma unroll
        for (int kk = 0; kk < 4; kk++) {
            uint32_t a[2][4];
#pragma unroll
            for (int mf = 0; mf < 2; mf++) {
                int r = rA + mf * 16;
                uint32_t ad = ab + r * 128 + (((kk * 2 + cselA) ^ (r & 7)) << 4);
                LDSM4(a[mf][0], a[mf][1], a[mf][2], a[mf][3], ad);
            }
#pragma unroll
            for (int p = 0; p < 2; p++) {
                int r0n = warpN * WNS + p * 16 + rB;
                uint32_t bd0 = bb + r0n * 128 + (((kk * 2 + cselB) ^ (r0n & 7)) << 4);
                uint32_t g0, g1, g2, g3;
                LDSM4(g0, g1, g2, g3, bd0);
                int r1n = r0n + NO2;
                uint32_t bd1 = bb + r1n * 128 + (((kk * 2 + cselB) ^ (r1n & 7)) << 4);
                uint32_t u0, u1, u2, u3;
                LDSM4(u0, u1, u2, u3, bd1);
#pragma unroll
                for (int mf = 0; mf < 2; mf++) {
                    mma_f16(c0[mf][2 * p],     a[mf], g0, g1);
                    mma_f16(c0[mf][2 * p + 1], a[mf], g2, g3);
                    mma_f16(c1[mf][2 * p],     a[mf], u0, u1);
                    mma_f16(c1[mf][2 * p + 1], a[mf], u2, u3);
                }
            }
        }
        __syncthreads();
    }

    const int lr = lane >> 2;
    if (MODE == 0) {
#pragma unroll
        for (int mf = 0; mf < 2; mf++) {
            int r0 = m0 + warpM * 32 + mf * 16 + lr;
#pragma unroll
            for (int nf = 0; nf < 4; nf++) {
                int col = nb * 64 + warpN * 32 + nf * 8 + 2 * lc;
#pragma unroll
                for (int hh = 0; hh < 2; hh++) {
                    float g0 = c0[mf][nf][2 * hh], g1 = c0[mf][nf][2 * hh + 1];
                    float u0 = c1[mf][nf][2 * hh], u1 = c1[mf][nf][2 * hh + 1];
                    float h0 = g0 * u0 / (1.f + expf(-g0));
                    float h1 = g1 * u1 / (1.f + expf(-g1));
                    __half2 hv = __floats2half2_rn(h0, h1);
                    *(__half2*)(d_hh + ((size_t)e * CAP + r0 + 8 * hh) * HDIM + col) = hv;
                }
            }
        }
    } else {
#pragma unroll
        for (int mf = 0; mf < 2; mf++) {
            int rl = warpM * 32 + mf * 16 + lr;
            int tok0 = s_tok[rl], tok1 = s_tok[rl + 8];
#pragma unroll
            for (int nf = 0; nf < 4; nf++) {
                int colA = nb * 128 + warpN * 64 + nf * 8 + 2 * lc;
                int colB = colA + 32;
                if (tok0 >= 0) {
                    *(float2*)(out + (size_t)tok0 * DDIM + colA) =
                        make_float2(c0[mf][nf][0], c0[mf][nf][1]);
                    *(float2*)(out + (size_t)tok0 * DDIM + colB) =
                        make_float2(c1[mf][nf][0], c1[mf][nf][1]);
                }
                if (tok1 >= 0) {
                    *(float2*)(out + (size_t)tok1 * DDIM + colA) =
                        make_float2(c0[mf][nf][2], c0[mf][nf][3]);
                    *(float2*)(out + (size_t)tok1 * DDIM + colB) =
                        make_float2(c1[mf][nf][2], c1[mf][nf][3]);
                }
            }
        }
    }
}

// ---------------- 6. finalize ----------------
__global__ void finalize_kernel(float* __restrict__ out)
{
    int i = blockIdx.x, t = threadIdx.x;
    int kp = d_keep[i];
    if (!kp)
        ((float4*)(out + (size_t)i * DDIM))[t] = make_float4(0.f, 0.f, 0.f, 0.f);
    if (t == 0) {
        out[OUT_TOP + i]  = (float)d_top[i];
        out[OUT_KEEP + i] = kp ? 1.f : 0.f;
    }
}

// ---------------- launch: 2-stream pipelined DAG ----------------------------
extern "C" void kernel_launch(void* const* d_in, const int* in_sizes, int n_in,
                              void* d_out, int out_size)
{
    const float* x   = (const float*)d_in[0];
    const float* Wg  = (const float*)d_in[1];
    const float* W13 = (const float*)d_in[2];
    const float* W2  = (const float*)d_in[3];
    float* out = (float*)d_out;

    cudaFuncSetAttribute(moe_gemm<0>, cudaFuncAttributeMaxDynamicSharedMemorySize, SMEM_G);
    cudaFuncSetAttribute(moe_gemm<1>, cudaFuncAttributeMaxDynamicSharedMemorySize, SMEM_G);

    __half* xh;   cudaGetSymbolAddress((void**)&xh,   d_xh);
    __half* w13h; cudaGetSymbolAddress((void**)&w13h, d_w13h);
    __half* w2h;  cudaGetSymbolAddress((void**)&w2h,  d_w2h);

    const int n4x   = NTOK * DDIM / 4;
    const int n4w1e = H2 * DDIM / 4;          // per-expert W13 chunk
    const int n4w2  = NE * DDIM * HDIM / 4;

    cudaStream_t s2;
    cudaEvent_t evFork, evScan, evW13hi, evG1[NE], evEnd;
    cudaStreamCreateWithFlags(&s2, cudaStreamNonBlocking);
    cudaEventCreateWithFlags(&evFork,   cudaEventDisableTiming);
    cudaEventCreateWithFlags(&evScan,   cudaEventDisableTiming);
    cudaEventCreateWithFlags(&evW13hi,  cudaEventDisableTiming);
    cudaEventCreateWithFlags(&evEnd,    cudaEventDisableTiming);
    for (int e = 0; e < NE; e++)
        cudaEventCreateWithFlags(&evG1[e], cudaEventDisableTiming);

    cudaEventRecord(evFork, 0);
    cudaStreamWaitEvent(s2, evFork, 0);

    // side stream: token path, W13 chunks 4..7, W2 cvt, small kernels
    cvt_kernel<<<(n4x + 255) / 256, 256, 0, s2>>>((const float4*)x, (uint2*)xh, n4x);
    router_kernel<<<NTOK / 8, 256, 0, s2>>>(x, Wg);
    scan_kernel<<<1, 1024, 0, s2>>>();
    cudaEventRecord(evScan, s2);
    for (int e = 4; e < NE; e++)
        cvt_kernel<<<(n4w1e + 255) / 256, 256, 0, s2>>>(
            (const float4*)(W13 + (size_t)e * H2 * DDIM),
            (uint2*)(w13h + (size_t)e * H2 * DDIM), n4w1e);
    cudaEventRecord(evW13hi, s2);
    cvt_kernel<<<(n4w2 + 255) / 256, 256, 0, s2>>>((const float4*)W2, (uint2*)w2h, n4w2);
    reduce_kernel<<<1, 1024, 0, s2>>>(out + OUT_AUX);
    finalize_kernel<<<NTOK, 256, 0, s2>>>(out);

    // main stream: W13 chunks 0..3, then gemm1 chain
    dim3 g1(CAP / 128, HDIM / 64);     // 10 x 88
    dim3 g2(CAP / 128, DDIM / 128);    // 10 x 8
    for (int e = 0; e < 4; e++)
        cvt_kernel<<<(n4w1e + 255) / 256, 256>>>(
            (const float4*)(W13 + (size_t)e * H2 * DDIM),
            (uint2*)(w13h + (size_t)e * H2 * DDIM), n4w1e);
    cudaStreamWaitEvent(0, evScan, 0);
    for (int e = 0; e < 4; e++) {
        moe_gemm<0><<<g1, 256, SMEM_G>>>(nullptr, e);
        cudaEventRecord(evG1[e], 0);
    }
    cudaStreamWaitEvent(0, evW13hi, 0);
    for (int e = 4; e < NE; e++) {
        moe_gemm<0><<<g1, 256, SMEM_G>>>(nullptr, e);
        cudaEventRecord(evG1[e], 0);
    }

    // side stream: gemm2 chain (w2h/reduce/finalize already ordered on s2)
    for (int e = 0; e < NE; e++) {
        cudaStreamWaitEvent(s2, evG1[e], 0);
        moe_gemm<1><<<g2, 256, SMEM_G, s2>>>(out, e);
    }
    cudaEventRecord(evEnd, s2);
    cudaStreamWaitEvent(0, evEnd, 0);

    cudaEventDestroy(evFork);
    cudaEventDestroy(evScan);
    cudaEventDestroy(evW13hi);
    cudaEventDestroy(evEnd);
    for (int e = 0; e < NE; e++) cudaEventDestroy(evG1[e]);
    cudaStreamDestroy(s2);
}

// round 11
// speedup vs baseline: 1.2441x; 1.2441x over previous
#include <cuda_runtime.h>
#include <cuda_fp16.h>
#include <cstdint>
#include <math.h>

#define NTOK 8192
#define NE   8
#define DDIM 1024
#define HDIM 5632
#define H2   (2*HDIM)
#define CAP  1280

#define OUT_AUX  8388608
#define OUT_TOP  (8388608 + 1)
#define OUT_KEEP (8388608 + 1 + NTOK)

// ---------------- scratch ----------------
__device__ float d_probs[NTOK * NE];
__device__ float d_z2[NTOK];
__device__ int   d_top[NTOK];
__device__ int   d_keep[NTOK];
__device__ int   d_gidx[NE * CAP];
__device__ int   d_counts[NE];
__device__ int   d_counts_cap[NE];
__device__ __align__(256) __half d_hh[(size_t)NE * CAP * HDIM];     // 115 MB
__device__ __align__(256) __half d_xh[(size_t)NTOK * DDIM];         //  17 MB
__device__ __align__(256) __half d_w13h[(size_t)NE * H2 * DDIM];    // 184 MB
__device__ __align__(256) __half d_w2h[(size_t)NE * DDIM * HDIM];   //  92 MB

// ---------------- helpers ----------------
__device__ __forceinline__ uint32_t smem_u32(const void* p) {
    uint32_t a;
    asm("{ .reg .u64 t; cvta.to.shared.u64 t, %1; cvt.u32.u64 %0, t; }"
        : "=r"(a) : "l"(p));
    return a;
}
__device__ __forceinline__ uint32_t h2_u32(__half2 h) {
    return *reinterpret_cast<uint32_t*>(&h);
}
__device__ __forceinline__ void mma_f16(float* c, const uint32_t* a,
                                        uint32_t b0, uint32_t b1) {
    asm volatile(
        "mma.sync.aligned.m16n8k16.row.col.f32.f16.f16.f32 "
        "{%0,%1,%2,%3}, {%4,%5,%6,%7}, {%8,%9}, {%0,%1,%2,%3};"
        : "+f"(c[0]), "+f"(c[1]), "+f"(c[2]), "+f"(c[3])
        : "r"(a[0]), "r"(a[1]), "r"(a[2]), "r"(a[3]), "r"(b0), "r"(b1));
}
#define LDSM4(r0, r1, r2, r3, a) \
    asm volatile("ldmatrix.sync.aligned.m8n8.x4.shared.b16 {%0,%1,%2,%3}, [%4];" \
                 : "=r"(r0), "=r"(r1), "=r"(r2), "=r"(r3) : "r"(a))
#define CP16(d, s) \
    asm volatile("cp.async.cg.shared.global [%0], [%1], 16;" :: "r"(d), "l"(s))
#define CPCOMMIT() asm volatile("cp.async.commit_group;")
#define CPWAIT1()  asm volatile("cp.async.wait_group 1;")

// ---------------- 0. fp32 -> fp16 conversion ----------------
__global__ void cvt_kernel(const float4* __restrict__ src,
                           uint2* __restrict__ dst, int n4)
{
    int i = blockIdx.x * blockDim.x + threadIdx.x;
    if (i < n4) {
        float4 v = src[i];
        __half2 lo = __floats2half2_rn(v.x, v.y);
        __half2 hi = __floats2half2_rn(v.z, v.w);
        dst[i] = make_uint2(h2_u32(lo), h2_u32(hi));
    }
}

// ---------------- 1. router ----------------
__global__ void router_kernel(const float* __restrict__ x,
                              const float* __restrict__ Wg)
{
    __shared__ float sWg[NE * DDIM];
    int t = threadIdx.x;
    for (int i = t; i < NE * DDIM; i += 256) sWg[i] = Wg[i];
    __syncthreads();

    int warp = t >> 5, lane = t & 31;
    int tok  = blockIdx.x * 8 + warp;
    const float* xr = x + (size_t)tok * DDIM;

    float acc[NE];
#pragma unroll
    for (int e = 0; e < NE; e++) acc[e] = 0.f;
    for (int k = lane; k < DDIM; k += 32) {
        float xv = xr[k];
#pragma unroll
        for (int e = 0; e < NE; e++) acc[e] = fmaf(xv, sWg[e * DDIM + k], acc[e]);
    }
#pragma unroll
    for (int e = 0; e < NE; e++) {
#pragma unroll
        for (int o = 16; o > 0; o >>= 1)
            acc[e] += __shfl_down_sync(0xffffffffu, acc[e], o);
    }
    if (lane == 0) {
        float m = acc[0]; int am = 0;
#pragma unroll
        for (int e = 1; e < NE; e++) if (acc[e] > m) { m = acc[e]; am = e; }
        float p[NE]; float s = 0.f;
#pragma unroll
        for (int e = 0; e < NE; e++) { p[e] = expf(acc[e] - m); s += p[e]; }
        float inv = 1.f / s;
#pragma unroll
        for (int e = 0; e < NE; e++) d_probs[tok * NE + e] = p[e] * inv;
        float z = m + logf(s);
        d_z2[tok] = z * z;
        d_top[tok] = am;
    }
}

// ---------------- 2. ordered capacity scan (shfl-based) ----------------
__global__ void scan_kernel()
{
    __shared__ unsigned long long wsum0[32], wsum1[32];
    __shared__ unsigned long long tile0, tile1;
    __shared__ int base[NE];
    const int t = threadIdx.x, lane = t & 31, wid = t >> 5;
    if (t < NE) base[t] = 0;
    __syncthreads();

    for (int tile = 0; tile < NTOK / 1024; tile++) {
        int i = tile * 1024 + t;
        int e = d_top[i];
        unsigned long long v0 = (e < 4)  ? (1ULL << (16 * e))       : 0ULL;
        unsigned long long v1 = (e >= 4) ? (1ULL << (16 * (e - 4))) : 0ULL;
        unsigned long long s0 = v0, s1 = v1;
#pragma unroll
        for (int o = 1; o < 32; o <<= 1) {
            unsigned long long a0 = __shfl_up_sync(0xffffffffu, s0, o);
            unsigned long long a1 = __shfl_up_sync(0xffffffffu, s1, o);
            if (lane >= o) { s0 += a0; s1 += a1; }
        }
        if (lane == 31) { wsum0[wid] = s0; wsum1[wid] = s1; }
        __syncthreads();
        if (wid == 0) {
            unsigned long long w0 = wsum0[lane], w1 = wsum1[lane];
            unsigned long long p0 = w0, p1 = w1;
#pragma unroll
            for (int o = 1; o < 32; o <<= 1) {
                unsigned long long a0 = __shfl_up_sync(0xffffffffu, p0, o);
                unsigned long long a1 = __shfl_up_sync(0xffffffffu, p1, o);
                if (lane >= o) { p0 += a0; p1 += a1; }
            }
            wsum0[lane] = p0 - w0;       // exclusive warp offsets
            wsum1[lane] = p1 - w1;
            if (lane == 31) { tile0 = p0; tile1 = p1; }
        }
        __syncthreads();
        unsigned long long inc = (e < 4) ? (s0 + wsum0[wid]) : (s1 + wsum1[wid]);
        int sh  = 16 * (e & 3);
        int pos = base[e] + (int)((inc >> sh) & 0xFFFFULL) - 1;
        int kp  = (pos < CAP) ? 1 : 0;
        d_keep[i] = kp;
        if (kp) d_gidx[e * CAP + pos] = i;
        __syncthreads();
        if (t < 4)      base[t] += (int)((tile0 >> (16 * t)) & 0xFFFFULL);
        else if (t < 8) base[t] += (int)((tile1 >> (16 * (t - 4))) & 0xFFFFULL);
        __syncthreads();
    }
    if (t < NE) {
        d_counts[t] = base[t];
        d_counts_cap[t] = base[t] < CAP ? base[t] : CAP;
    }
}

// ---------------- 3. aux loss ----------------
__global__ void reduce_kernel(float* __restrict__ out_aux)
{
    __shared__ float sm[1024];
    __shared__ float pe[NE];
    int t = threadIdx.x;
    float pp[NE];
#pragma unroll
    for (int e = 0; e < NE; e++) pp[e] = 0.f;
    float zz = 0.f;
    for (int i = t; i < NTOK; i += 1024) {
#pragma unroll
        for (int e = 0; e < NE; e++) pp[e] += d_probs[i * NE + e];
        zz += d_z2[i];
    }
#pragma unroll
    for (int e = 0; e < NE; e++) {
        sm[t] = pp[e]; __syncthreads();
        for (int o = 512; o > 0; o >>= 1) {
            if (t < o) sm[t] += sm[t + o];
            __syncthreads();
        }
        if (t == 0) pe[e] = sm[0];
        __syncthreads();
    }
    sm[t] = zz; __syncthreads();
    for (int o = 512; o > 0; o >>= 1) {
        if (t < o) sm[t] += sm[t + o];
        __syncthreads();
    }
    if (t == 0) {
        float bal = 0.f;
        for (int e = 0; e < NE; e++)
            bal += (pe[e] / (float)NTOK) * ((float)d_counts[e] / (float)NTOK);
        bal *= 0.01f * (float)NE;
        out_aux[0] = bal + (sm[0] / (float)NTOK) * 0.001f;
    }
}

// ---------------- 4/5. fp16 mma.sync GEMMs ---------------------------------
// MODE 0: h = silu(xe@Wg^T)*(xe@Wu^T); grid.z = expert
// MODE 1: out += h@W2^T (2-way split-K, atomicAdd; grid.z = expert + 8*khalf)
//         bit-deterministic: exactly 2 commutative fp adds per element.
#define STG_B  32768               // bytes per stage (A 16KB + B 16KB)
#define SMEM_G (3 * STG_B)         // 98304 B
#define KT2H   (HDIM / 64 / 2)     // 44 k-iterations per gemm2 half

template<int MODE>
__global__ __launch_bounds__(256, 2)
void moe_gemm(float* __restrict__ out)
{
    constexpr int KT  = (MODE == 0) ? DDIM / 64 : KT2H;
    constexpr int WNS = (MODE == 0) ? 32 : 64;   // warpN stride (n cols)
    constexpr int NO2 = (MODE == 0) ? 64 : 32;   // row offset of second acc set

    extern __shared__ char smc[];
    __shared__ int s_tok[128];

    const int t = threadIdx.x, wid = t >> 5, lane = t & 31;
    const int lc = lane & 3;
    const int warpM = wid & 3, warpN = wid >> 2;
    const int e  = (MODE == 0) ? blockIdx.z : (blockIdx.z & 7);
    const int kh = (MODE == 0) ? 0 : (blockIdx.z >> 3);
    const int m0 = blockIdx.x * 128, nb = blockIdx.y;

    const int cc = d_counts_cap[e];
    if (m0 >= cc) return;            // dead capacity rows: outputs never read

    if (t < 128)
        s_tok[t] = (m0 + t < cc) ? d_gidx[e * CAP + m0 + t] : ((MODE == 0) ? 0 : -1);
    __syncthreads();

    const uint32_t sbase = smem_u32(smc);
    const int lrow = t >> 1;           // loader row 0..127
    const int q0l  = (t & 1) * 4;      // first of 4 chunks
    const int ktoff = kh * KT2H;

    auto load_stage = [&](int kt, int s) {
        const uint32_t ab = sbase + (uint32_t)s * STG_B;
        const uint32_t bb = ab + 16384;
        const int k0 = (ktoff + kt) * 64;
#pragma unroll
        for (int c = 0; c < 4; c++) {
            int q = q0l + c;
            uint32_t dsw = (uint32_t)(lrow * 128 + ((q ^ (lrow & 7)) << 4));
            const __half* srcA;
            if (MODE == 0)
                srcA = d_xh + (size_t)s_tok[lrow] * DDIM + k0 + q * 8;
            else
                srcA = d_hh + ((size_t)e * CAP + m0 + lrow) * HDIM + k0 + q * 8;
            CP16(ab + dsw, srcA);
            const __half* srcB;
            if (MODE == 0) {
                int wr = (lrow < 64) ? (nb * 64 + lrow)
                                     : (HDIM + nb * 64 + lrow - 64);
                srcB = d_w13h + ((size_t)e * H2 + wr) * DDIM + k0 + q * 8;
            } else {
                srcB = d_w2h + ((size_t)e * DDIM + nb * 128 + lrow) * HDIM + k0 + q * 8;
            }
            CP16(bb + dsw, srcB);
        }
    };

    float c0[2][4][4], c1[2][4][4];
#pragma unroll
    for (int a = 0; a < 2; a++)
#pragma unroll
        for (int b = 0; b < 4; b++)
#pragma unroll
            for (int r = 0; r < 4; r++) { c0[a][b][r] = 0.f; c1[a][b][r] = 0.f; }

    const int rA  = warpM * 32 + (lane & 15);        // + mf*16
    const int cselA = lane >> 4;
    const int rB  = (lane & 7) + ((lane & 16) >> 1);
    const int cselB = (lane >> 3) & 1;

    load_stage(0, 0); CPCOMMIT();
    load_stage(1, 1); CPCOMMIT();

    for (int kt = 0; kt < KT; kt++) {
        CPWAIT1();
        __syncthreads();
        if (kt + 2 < KT) load_stage(kt + 2, (kt + 2) % 3);
        CPCOMMIT();

        const uint32_t ab = sbase + (uint32_t)(kt % 3) * STG_B;
        const uint32_t bb = ab + 16384;
#pragma unroll
        for (int kk = 0; kk < 4; kk++) {
            uint32_t a[2][4];
#pragma unroll
            for (int mf = 0; mf < 2; mf++) {
                int r = rA + mf * 16;
                uint32_t ad = ab + r * 128 + (((kk * 2 + cselA) ^ (r & 7)) << 4);
                LDSM4(a[mf][0], a[mf][1], a[mf][2], a[mf][3], ad);
            }
#pragma unroll
            for (int p = 0; p < 2; p++) {
                int r0n = warpN * WNS + p * 16 + rB;
                uint32_t bd0 = bb + r0n * 128 + (((kk * 2 + cselB) ^ (r0n & 7)) << 4);
                uint32_t g0, g1, g2, g3;
                LDSM4(g0, g1, g2, g3, bd0);
                int r1n = r0n + NO2;
                uint32_t bd1 = bb + r1n * 128 + (((kk * 2 + cselB) ^ (r1n & 7)) << 4);
                uint32_t u0, u1, u2, u3;
                LDSM4(u0, u1, u2, u3, bd1);
#pragma unroll
                for (int mf = 0; mf < 2; mf++) {
                    mma_f16(c0[mf][2 * p],     a[mf], g0, g1);
                    mma_f16(c0[mf][2 * p + 1], a[mf], g2, g3);
                    mma_f16(c1[mf][2 * p],     a[mf], u0, u1);
                    mma_f16(c1[mf][2 * p + 1], a[mf], u2, u3);
                }
            }
        }
        __syncthreads();
    }

    const int lr = lane >> 2;
    if (MODE == 0) {
#pragma unroll
        for (int mf = 0; mf < 2; mf++) {
            int r0 = m0 + warpM * 32 + mf * 16 + lr;
#pragma unroll
            for (int nf = 0; nf < 4; nf++) {
                int col = nb * 64 + warpN * 32 + nf * 8 + 2 * lc;
#pragma unroll
                for (int hh = 0; hh < 2; hh++) {
                    float g0 = c0[mf][nf][2 * hh], g1 = c0[mf][nf][2 * hh + 1];
                    float u0 = c1[mf][nf][2 * hh], u1 = c1[mf][nf][2 * hh + 1];
                    float h0 = g0 * u0 / (1.f + expf(-g0));
                    float h1 = g1 * u1 / (1.f + expf(-g1));
                    __half2 hv = __floats2half2_rn(h0, h1);
                    *(__half2*)(d_hh + ((size_t)e * CAP + r0 + 8 * hh) * HDIM + col) = hv;
                }
            }
        }
    } else {
        // accumulate split-K partials (2 commutative adds -> deterministic)
#pragma unroll
        for (int mf = 0; mf < 2; mf++) {
            int rl = warpM * 32 + mf * 16 + lr;
            int tok0 = s_tok[rl], tok1 = s_tok[rl + 8];
#pragma unroll
            for (int nf = 0; nf < 4; nf++) {
                int colA = nb * 128 + warpN * 64 + nf * 8 + 2 * lc;
                int colB = colA + 32;
                if (tok0 >= 0) {
                    float* p = out + (size_t)tok0 * DDIM;
                    atomicAdd(p + colA,     c0[mf][nf][0]);
                    atomicAdd(p + colA + 1, c0[mf][nf][1]);
                    atomicAdd(p + colB,     c1[mf][nf][0]);
                    atomicAdd(p + colB + 1, c1[mf][nf][1]);
                }
                if (tok1 >= 0) {
                    float* p = out + (size_t)tok1 * DDIM;
                    atomicAdd(p + colA,     c0[mf][nf][2]);
                    atomicAdd(p + colA + 1, c0[mf][nf][3]);
                    atomicAdd(p + colB,     c1[mf][nf][2]);
                    atomicAdd(p + colB + 1, c1[mf][nf][3]);
                }
            }
        }
    }
}

// ---------------- 6. finalize: zero ALL token rows + top/keep --------------
__global__ void finalize_kernel(float* __restrict__ out)
{
    int i = blockIdx.x, t = threadIdx.x;
    ((float4*)(out + (size_t)i * DDIM))[t] = make_float4(0.f, 0.f, 0.f, 0.f);
    if (t == 0) {
        int kp = d_keep[i];
        out[OUT_TOP + i]  = (float)d_top[i];
        out[OUT_KEEP + i] = kp ? 1.f : 0.f;
    }
}

// ---------------- launch: two-stream captured DAG ---------------------------
extern "C" void kernel_launch(void* const* d_in, const int* in_sizes, int n_in,
                              void* d_out, int out_size)
{
    const float* x   = (const float*)d_in[0];
    const float* Wg  = (const float*)d_in[1];
    const float* W13 = (const float*)d_in[2];
    const float* W2  = (const float*)d_in[3];
    float* out = (float*)d_out;

    cudaFuncSetAttribute(moe_gemm<0>, cudaFuncAttributeMaxDynamicSharedMemorySize, SMEM_G);
    cudaFuncSetAttribute(moe_gemm<1>, cudaFuncAttributeMaxDynamicSharedMemorySize, SMEM_G);

    __half* xh;   cudaGetSymbolAddress((void**)&xh,   d_xh);
    __half* w13h; cudaGetSymbolAddress((void**)&w13h, d_w13h);
    __half* w2h;  cudaGetSymbolAddress((void**)&w2h,  d_w2h);

    const int n4x  = NTOK * DDIM / 4;
    const int n4w1 = NE * H2 * DDIM / 4;
    const int n4w2 = NE * DDIM * HDIM / 4;

    cudaStream_t s2;
    cudaEvent_t evFork, evJoin1, evJoin2;
    cudaStreamCreateWithFlags(&s2, cudaStreamNonBlocking);
    cudaEventCreateWithFlags(&evFork,  cudaEventDisableTiming);
    cudaEventCreateWithFlags(&evJoin1, cudaEventDisableTiming);
    cudaEventCreateWithFlags(&evJoin2, cudaEventDisableTiming);

    // fork
    cudaEventRecord(evFork, 0);
    cudaStreamWaitEvent(s2, evFork, 0);

    // side stream: token path + small kernels + W2 conversion
    cvt_kernel<<<(n4x + 255) / 256, 256, 0, s2>>>((const float4*)x, (uint2*)xh, n4x);
    router_kernel<<<NTOK / 8, 256, 0, s2>>>(x, Wg);
    scan_kernel<<<1, 1024, 0, s2>>>();
    cudaEventRecord(evJoin1, s2);               // gemm1 deps: xh + gidx/counts
    reduce_kernel<<<1, 1024, 0, s2>>>(out + OUT_AUX);
    finalize_kernel<<<NTOK, 256, 0, s2>>>(out); // zeroes rows (gemm2 accumulates)
    cvt_kernel<<<(n4w2 + 255) / 256, 256, 0, s2>>>((const float4*)W2, (uint2*)w2h, n4w2);
    cudaEventRecord(evJoin2, s2);               // gemm2 deps: w2h + zeroed out

    // main stream: W13 conversion runs concurrent with side stream
    cvt_kernel<<<(n4w1 + 255) / 256, 256>>>((const float4*)W13, (uint2*)w13h, n4w1);

    cudaStreamWaitEvent(0, evJoin1, 0);
    dim3 g1(CAP / 128, HDIM / 64, NE);          // 10 x 88 x 8
    moe_gemm<0><<<g1, 256, SMEM_G>>>(nullptr);

    cudaStreamWaitEvent(0, evJoin2, 0);
    dim3 g2(CAP / 128, DDIM / 128, 2 * NE);     // 10 x 8 x 16 (split-K)
    moe_gemm<1><<<g2, 256, SMEM_G>>>(out);

    cudaEventDestroy(evFork);
    cudaEventDestroy(evJoin1);
    cudaEventDestroy(evJoin2);
    cudaStreamDestroy(s2);
}

// round 12
// speedup vs baseline: 1.2652x; 1.0170x over previous
#include <cuda_runtime.h>
#include <cuda_fp16.h>
#include <cstdint>
#include <math.h>

#define NTOK 8192
#define NE   8
#define DDIM 1024
#define HDIM 5632
#define H2   (2*HDIM)
#define CAP  1280

#define OUT_AUX  8388608
#define OUT_TOP  (8388608 + 1)
#define OUT_KEEP (8388608 + 1 + NTOK)

// ---------------- scratch ----------------
__device__ float d_probs[NTOK * NE];
__device__ float d_z2[NTOK];
__device__ int   d_top[NTOK];
__device__ int   d_keep[NTOK];
__device__ int   d_gidx[NE * CAP];
__device__ int   d_counts[NE];
__device__ int   d_counts_cap[NE];
__device__ __align__(256) __half d_hh[(size_t)NE * CAP * HDIM];     // 115 MB
__device__ __align__(256) __half d_xh[(size_t)NTOK * DDIM];         //  17 MB
__device__ __align__(256) __half d_w13h[(size_t)NE * H2 * DDIM];    // 184 MB
__device__ __align__(256) __half d_w2h[(size_t)NE * DDIM * HDIM];   //  92 MB

// ---------------- helpers ----------------
__device__ __forceinline__ uint32_t smem_u32(const void* p) {
    uint32_t a;
    asm("{ .reg .u64 t; cvta.to.shared.u64 t, %1; cvt.u32.u64 %0, t; }"
        : "=r"(a) : "l"(p));
    return a;
}
__device__ __forceinline__ uint32_t h2_u32(__half2 h) {
    return *reinterpret_cast<uint32_t*>(&h);
}
__device__ __forceinline__ void mma_f16(float* c, const uint32_t* a,
                                        uint32_t b0, uint32_t b1) {
    asm volatile(
        "mma.sync.aligned.m16n8k16.row.col.f32.f16.f16.f32 "
        "{%0,%1,%2,%3}, {%4,%5,%6,%7}, {%8,%9}, {%0,%1,%2,%3};"
        : "+f"(c[0]), "+f"(c[1]), "+f"(c[2]), "+f"(c[3])
        : "r"(a[0]), "r"(a[1]), "r"(a[2]), "r"(a[3]), "r"(b0), "r"(b1));
}
#define LDSM4(r0, r1, r2, r3, a) \
    asm volatile("ldmatrix.sync.aligned.m8n8.x4.shared.b16 {%0,%1,%2,%3}, [%4];" \
                 : "=r"(r0), "=r"(r1), "=r"(r2), "=r"(r3) : "r"(a))
#define CP16(d, s) \
    asm volatile("cp.async.cg.shared.global [%0], [%1], 16;" :: "r"(d), "l"(s))
#define CPCOMMIT() asm volatile("cp.async.commit_group;")
#define CPWAIT1()  asm volatile("cp.async.wait_group 1;")

// ---------------- 0. fp32 -> fp16 conversion ----------------
__global__ void cvt_kernel(const float4* __restrict__ src,
                           uint2* __restrict__ dst, int n4)
{
    int i = blockIdx.x * blockDim.x + threadIdx.x;
    if (i < n4) {
        float4 v = src[i];
        __half2 lo = __floats2half2_rn(v.x, v.y);
        __half2 hi = __floats2half2_rn(v.z, v.w);
        dst[i] = make_uint2(h2_u32(lo), h2_u32(hi));
    }
}

// ---------------- 1. router ----------------
__global__ void router_kernel(const float* __restrict__ x,
                              const float* __restrict__ Wg)
{
    __shared__ float sWg[NE * DDIM];
    int t = threadIdx.x;
    for (int i = t; i < NE * DDIM; i += 256) sWg[i] = Wg[i];
    __syncthreads();

    int warp = t >> 5, lane = t & 31;
    int tok  = blockIdx.x * 8 + warp;
    const float* xr = x + (size_t)tok * DDIM;

    float acc[NE];
#pragma unroll
    for (int e = 0; e < NE; e++) acc[e] = 0.f;
    for (int k = lane; k < DDIM; k += 32) {
        float xv = xr[k];
#pragma unroll
        for (int e = 0; e < NE; e++) acc[e] = fmaf(xv, sWg[e * DDIM + k], acc[e]);
    }
#pragma unroll
    for (int e = 0; e < NE; e++) {
#pragma unroll
        for (int o = 16; o > 0; o >>= 1)
            acc[e] += __shfl_down_sync(0xffffffffu, acc[e], o);
    }
    if (lane == 0) {
        float m = acc[0]; int am = 0;
#pragma unroll
        for (int e = 1; e < NE; e++) if (acc[e] > m) { m = acc[e]; am = e; }
        float p[NE]; float s = 0.f;
#pragma unroll
        for (int e = 0; e < NE; e++) { p[e] = expf(acc[e] - m); s += p[e]; }
        float inv = 1.f / s;
#pragma unroll
        for (int e = 0; e < NE; e++) d_probs[tok * NE + e] = p[e] * inv;
        float z = m + logf(s);
        d_z2[tok] = z * z;
        d_top[tok] = am;
    }
}

// ---------------- 2. ordered capacity scan (shfl-based) ----------------
__global__ void scan_kernel()
{
    __shared__ unsigned long long wsum0[32], wsum1[32];
    __shared__ unsigned long long tile0, tile1;
    __shared__ int base[NE];
    const int t = threadIdx.x, lane = t & 31, wid = t >> 5;
    if (t < NE) base[t] = 0;
    __syncthreads();

    for (int tile = 0; tile < NTOK / 1024; tile++) {
        int i = tile * 1024 + t;
        int e = d_top[i];
        unsigned long long v0 = (e < 4)  ? (1ULL << (16 * e))       : 0ULL;
        unsigned long long v1 = (e >= 4) ? (1ULL << (16 * (e - 4))) : 0ULL;
        unsigned long long s0 = v0, s1 = v1;
#pragma unroll
        for (int o = 1; o < 32; o <<= 1) {
            unsigned long long a0 = __shfl_up_sync(0xffffffffu, s0, o);
            unsigned long long a1 = __shfl_up_sync(0xffffffffu, s1, o);
            if (lane >= o) { s0 += a0; s1 += a1; }
        }
        if (lane == 31) { wsum0[wid] = s0; wsum1[wid] = s1; }
        __syncthreads();
        if (wid == 0) {
            unsigned long long w0 = wsum0[lane], w1 = wsum1[lane];
            unsigned long long p0 = w0, p1 = w1;
#pragma unroll
            for (int o = 1; o < 32; o <<= 1) {
                unsigned long long a0 = __shfl_up_sync(0xffffffffu, p0, o);
                unsigned long long a1 = __shfl_up_sync(0xffffffffu, p1, o);
                if (lane >= o) { p0 += a0; p1 += a1; }
            }
            wsum0[lane] = p0 - w0;       // exclusive warp offsets
            wsum1[lane] = p1 - w1;
            if (lane == 31) { tile0 = p0; tile1 = p1; }
        }
        __syncthreads();
        unsigned long long inc = (e < 4) ? (s0 + wsum0[wid]) : (s1 + wsum1[wid]);
        int sh  = 16 * (e & 3);
        int pos = base[e] + (int)((inc >> sh) & 0xFFFFULL) - 1;
        int kp  = (pos < CAP) ? 1 : 0;
        d_keep[i] = kp;
        if (kp) d_gidx[e * CAP + pos] = i;
        __syncthreads();
        if (t < 4)      base[t] += (int)((tile0 >> (16 * t)) & 0xFFFFULL);
        else if (t < 8) base[t] += (int)((tile1 >> (16 * (t - 4))) & 0xFFFFULL);
        __syncthreads();
    }
    if (t < NE) {
        d_counts[t] = base[t];
        d_counts_cap[t] = base[t] < CAP ? base[t] : CAP;
    }
}

// ---------------- 3. aux loss ----------------
__global__ void reduce_kernel(float* __restrict__ out_aux)
{
    __shared__ float sm[1024];
    __shared__ float pe[NE];
    int t = threadIdx.x;
    float pp[NE];
#pragma unroll
    for (int e = 0; e < NE; e++) pp[e] = 0.f;
    float zz = 0.f;
    for (int i = t; i < NTOK; i += 1024) {
#pragma unroll
        for (int e = 0; e < NE; e++) pp[e] += d_probs[i * NE + e];
        zz += d_z2[i];
    }
#pragma unroll
    for (int e = 0; e < NE; e++) {
        sm[t] = pp[e]; __syncthreads();
        for (int o = 512; o > 0; o >>= 1) {
            if (t < o) sm[t] += sm[t + o];
            __syncthreads();
        }
        if (t == 0) pe[e] = sm[0];
        __syncthreads();
    }
    sm[t] = zz; __syncthreads();
    for (int o = 512; o > 0; o >>= 1) {
        if (t < o) sm[t] += sm[t + o];
        __syncthreads();
    }
    if (t == 0) {
        float bal = 0.f;
        for (int e = 0; e < NE; e++)
            bal += (pe[e] / (float)NTOK) * ((float)d_counts[e] / (float)NTOK);
        bal *= 0.01f * (float)NE;
        out_aux[0] = bal + (sm[0] / (float)NTOK) * 0.001f;
    }
}

// ---------------- 4/5. fp16 mma.sync GEMMs, ldmatrix + cp.async -----------
// 3-stage ring: single __syncthreads per k-iteration (the bottom barrier is
// redundant — the writer of stage (kt+2)%3 never conflicts with readers of
// kt%3 or (kt+1)%3, and reuse of stage kt%3 at kt+1 is ordered by the top
// CPWAIT+sync of kt+1).
#define STG_B  32768               // bytes per stage (A 16KB + B 16KB)
#define SMEM_G (3 * STG_B)         // 98304 B

template<int MODE>
__global__ __launch_bounds__(256, 2)
void moe_gemm(float* __restrict__ out)
{
    constexpr int KT  = (MODE == 0) ? DDIM / 64 : HDIM / 64;
    constexpr int WNS = (MODE == 0) ? 32 : 64;   // warpN stride (n cols)
    constexpr int NO2 = (MODE == 0) ? 64 : 32;   // row offset of second acc set

    extern __shared__ char smc[];
    __shared__ int s_tok[128];

    const int t = threadIdx.x, wid = t >> 5, lane = t & 31;
    const int lc = lane & 3;
    const int warpM = wid & 3, warpN = wid >> 2;
    const int e = blockIdx.z, m0 = blockIdx.x * 128, nb = blockIdx.y;

    const int cc = d_counts_cap[e];
    if (m0 >= cc) return;            // dead capacity rows: outputs never read

    if (t < 128)
        s_tok[t] = (m0 + t < cc) ? d_gidx[e * CAP + m0 + t] : ((MODE == 0) ? 0 : -1);
    __syncthreads();

    const uint32_t sbase = smem_u32(smc);
    const int lrow = t >> 1;           // loader row 0..127
    const int q0l  = (t & 1) * 4;      // first of 4 chunks

    auto load_stage = [&](int kt, int s) {
        const uint32_t ab = sbase + (uint32_t)s * STG_B;
        const uint32_t bb = ab + 16384;
        const int k0 = kt * 64;
#pragma unroll
        for (int c = 0; c < 4; c++) {
            int q = q0l + c;
            uint32_t dsw = (uint32_t)(lrow * 128 + ((q ^ (lrow & 7)) << 4));
            const __half* srcA;
            if (MODE == 0)
                srcA = d_xh + (size_t)s_tok[lrow] * DDIM + k0 + q * 8;
            else
                srcA = d_hh + ((size_t)e * CAP + m0 + lrow) * HDIM + k0 + q * 8;
            CP16(ab + dsw, srcA);
            const __half* srcB;
            if (MODE == 0) {
                int wr = (lrow < 64) ? (nb * 64 + lrow)
                                     : (HDIM + nb * 64 + lrow - 64);
                srcB = d_w13h + ((size_t)e * H2 + wr) * DDIM + k0 + q * 8;
            } else {
                srcB = d_w2h + ((size_t)e * DDIM + nb * 128 + lrow) * HDIM + k0 + q * 8;
            }
            CP16(bb + dsw, srcB);
        }
    };

    float c0[2][4][4], c1[2][4][4];
#pragma unroll
    for (int a = 0; a < 2; a++)
#pragma unroll
        for (int b = 0; b < 4; b++)
#pragma unroll
            for (int r = 0; r < 4; r++) { c0[a][b][r] = 0.f; c1[a][b][r] = 0.f; }

    const int rA  = warpM * 32 + (lane & 15);        // + mf*16
    const int cselA = lane >> 4;
    const int rB  = (lane & 7) + ((lane & 16) >> 1);
    const int cselB = (lane >> 3) & 1;

    load_stage(0, 0); CPCOMMIT();
    load_stage(1, 1); CPCOMMIT();

    for (int kt = 0; kt < KT; kt++) {
        CPWAIT1();
        __syncthreads();
        if (kt + 2 < KT) load_stage(kt + 2, (kt + 2) % 3);
        CPCOMMIT();

        const uint32_t ab = sbase + (uint32_t)(kt % 3) * STG_B;
        const uint32_t bb = ab + 16384;
#pragma unroll
        for (int kk = 0; kk < 4; kk++) {
            uint32_t a[2][4];
#pragma unroll
            for (int mf = 0; mf < 2; mf++) {
                int r = rA + mf * 16;
                uint32_t ad = ab + r * 128 + (((kk * 2 + cselA) ^ (r & 7)) << 4);
                LDSM4(a[mf][0], a[mf][1], a[mf][2], a[mf][3], ad);
            }
#pragma unroll
            for (int p = 0; p < 2; p++) {
                int r0n = warpN * WNS + p * 16 + rB;
                uint32_t bd0 = bb + r0n * 128 + (((kk * 2 + cselB) ^ (r0n & 7)) << 4);
                uint32_t g0, g1, g2, g3;
                LDSM4(g0, g1, g2, g3, bd0);
                int r1n = r0n + NO2;
                uint32_t bd1 = bb + r1n * 128 + (((kk * 2 + cselB) ^ (r1n & 7)) << 4);
                uint32_t u0, u1, u2, u3;
                LDSM4(u0, u1, u2, u3, bd1);
#pragma unroll
                for (int mf = 0; mf < 2; mf++) {
                    mma_f16(c0[mf][2 * p],     a[mf], g0, g1);
                    mma_f16(c0[mf][2 * p + 1], a[mf], g2, g3);
                    mma_f16(c1[mf][2 * p],     a[mf], u0, u1);
                    mma_f16(c1[mf][2 * p + 1], a[mf], u2, u3);
                }
            }
        }
        // no bottom barrier: stage reuse is ordered by next iteration's
        // CPWAIT1 + __syncthreads (see comment above)
    }

    const int lr = lane >> 2;
    if (MODE == 0) {
#pragma unroll
        for (int mf = 0; mf < 2; mf++) {
            int r0 = m0 + warpM * 32 + mf * 16 + lr;
#pragma unroll
            for (int nf = 0; nf < 4; nf++) {
                int col = nb * 64 + warpN * 32 + nf * 8 + 2 * lc;
#pragma unroll
                for (int hh = 0; hh < 2; hh++) {
                    float g0 = c0[mf][nf][2 * hh], g1 = c0[mf][nf][2 * hh + 1];
                    float u0 = c1[mf][nf][2 * hh], u1 = c1[mf][nf][2 * hh + 1];
                    float h0 = g0 * u0 / (1.f + expf(-g0));
                    float h1 = g1 * u1 / (1.f + expf(-g1));
                    __half2 hv = __floats2half2_rn(h0, h1);
                    *(__half2*)(d_hh + ((size_t)e * CAP + r0 + 8 * hh) * HDIM + col) = hv;
                }
            }
        }
    } else {
#pragma unroll
        for (int mf = 0; mf < 2; mf++) {
            int rl = warpM * 32 + mf * 16 + lr;
            int tok0 = s_tok[rl], tok1 = s_tok[rl + 8];
#pragma unroll
            for (int nf = 0; nf < 4; nf++) {
                int colA = nb * 128 + warpN * 64 + nf * 8 + 2 * lc;
                int colB = colA + 32;
                if (tok0 >= 0) {
                    *(float2*)(out + (size_t)tok0 * DDIM + colA) =
                        make_float2(c0[mf][nf][0], c0[mf][nf][1]);
                    *(float2*)(out + (size_t)tok0 * DDIM + colB) =
                        make_float2(c1[mf][nf][0], c1[mf][nf][1]);
                }
                if (tok1 >= 0) {
                    *(float2*)(out + (size_t)tok1 * DDIM + colA) =
                        make_float2(c0[mf][nf][2], c0[mf][nf][3]);
                    *(float2*)(out + (size_t)tok1 * DDIM + colB) =
                        make_float2(c1[mf][nf][2], c1[mf][nf][3]);
                }
            }
        }
    }
}

// ---------------- 6. finalize (zero dropped rows, top/keep) ----------------
__global__ void finalize_kernel(float* __restrict__ out)
{
    int i = blockIdx.x, t = threadIdx.x;
    int kp = d_keep[i];
    if (!kp)
        ((float4*)(out + (size_t)i * DDIM))[t] = make_float4(0.f, 0.f, 0.f, 0.f);
    if (t == 0) {
        out[OUT_TOP + i]  = (float)d_top[i];
        out[OUT_KEEP + i] = kp ? 1.f : 0.f;
    }
}

// ---------------- launch: two-stream captured DAG ---------------------------
extern "C" void kernel_launch(void* const* d_in, const int* in_sizes, int n_in,
                              void* d_out, int out_size)
{
    const float* x   = (const float*)d_in[0];
    const float* Wg  = (const float*)d_in[1];
    const float* W13 = (const float*)d_in[2];
    const float* W2  = (const float*)d_in[3];
    float* out = (float*)d_out;

    cudaFuncSetAttribute(moe_gemm<0>, cudaFuncAttributeMaxDynamicSharedMemorySize, SMEM_G);
    cudaFuncSetAttribute(moe_gemm<1>, cudaFuncAttributeMaxDynamicSharedMemorySize, SMEM_G);

    __half* xh;   cudaGetSymbolAddress((void**)&xh,   d_xh);
    __half* w13h; cudaGetSymbolAddress((void**)&w13h, d_w13h);
    __half* w2h;  cudaGetSymbolAddress((void**)&w2h,  d_w2h);

    const int n4x  = NTOK * DDIM / 4;
    const int n4w1 = NE * H2 * DDIM / 4;
    const int n4w2 = NE * DDIM * HDIM / 4;

    cudaStream_t s2;
    cudaEvent_t evFork, evJoin1, evJoin2;
    cudaStreamCreateWithFlags(&s2, cudaStreamNonBlocking);
    cudaEventCreateWithFlags(&evFork,  cudaEventDisableTiming);
    cudaEventCreateWithFlags(&evJoin1, cudaEventDisableTiming);
    cudaEventCreateWithFlags(&evJoin2, cudaEventDisableTiming);

    // fork
    cudaEventRecord(evFork, 0);
    cudaStreamWaitEvent(s2, evFork, 0);

    // side stream: token path + small kernels + W2 conversion
    cvt_kernel<<<(n4x + 255) / 256, 256, 0, s2>>>((const float4*)x, (uint2*)xh, n4x);
    router_kernel<<<NTOK / 8, 256, 0, s2>>>(x, Wg);
    scan_kernel<<<1, 1024, 0, s2>>>();
    cudaEventRecord(evJoin1, s2);               // gemm1 deps: xh + gidx/counts
    reduce_kernel<<<1, 1024, 0, s2>>>(out + OUT_AUX);
    finalize_kernel<<<NTOK, 256, 0, s2>>>(out); // zeros dropped rows, top/keep
    cvt_kernel<<<(n4w2 + 255) / 256, 256, 0, s2>>>((const float4*)W2, (uint2*)w2h, n4w2);
    cudaEventRecord(evJoin2, s2);               // gemm2 deps: w2h (+ ordering)

    // main stream: W13 conversion runs concurrent with side stream
    cvt_kernel<<<(n4w1 + 255) / 256, 256>>>((const float4*)W13, (uint2*)w13h, n4w1);

    cudaStreamWaitEvent(0, evJoin1, 0);
    dim3 g1(CAP / 128, HDIM / 64, NE);          // 10 x 88 x 8
    moe_gemm<0><<<g1, 256, SMEM_G>>>(nullptr);

    cudaStreamWaitEvent(0, evJoin2, 0);
    dim3 g2(CAP / 128, DDIM / 128, NE);         // 10 x 8 x 8
    moe_gemm<1><<<g2, 256, SMEM_G>>>(out);

    cudaEventDestroy(evFork);
    cudaEventDestroy(evJoin1);
    cudaEventDestroy(evJoin2);
    cudaStreamDestroy(s2);
}